// round 7
// baseline (speedup 1.0000x reference)
#include <cuda_runtime.h>

// RNN_26938034880941: vanilla tanh RNN  B=4096, S=512, I=1, H=16, O=1
// Round 7: SHFL.IDX exchange — NO shared memory in the recurrence.
//   16 lanes/batch (lane owns hidden unit j), 2 batches/warp, 512x128 grid.
//   After tanh, all lanes gather the 16 h values via 16 register shuffles
//   (width=16), eliminating the STS->LDS smem round-trip (no store-forward
//   on sm_103a) that profiling shows dominates T_step.
//   Dot: scalar FFMA, 4 chains of 4, qx folded into chain-0 init, shfl order
//   matched to chain consumption order (k0,k1,k2,k3 head the 4 chains).
//   tanh.approx for steps 0..447, exact ex2/rcp for last 64 (error decays).
//   x via LDG.128 quads with depth-2 register prefetch.

#define TWO_LOG2E 2.88539008177792681472f  // 2*log2(e)

__global__ void __launch_bounds__(128)
rnn_kernel(const float* __restrict__ x,     // [4096,512,1]
           const float* __restrict__ Wih,   // [16,1]
           const float* __restrict__ Whh,   // [16,16]
           const float* __restrict__ bih,   // [16]
           const float* __restrict__ bhh,   // [16]
           const float* __restrict__ Wfc,   // [1,16]
           const float* __restrict__ bfc,   // [1]
           float* __restrict__ out)         // [4096,1]
{
    const int tid  = threadIdx.x;
    const int lane = tid & 31;
    const int warp = tid >> 5;
    const int g    = lane >> 4;   // group within warp (0/1)
    const int j    = lane & 15;   // hidden unit owned by this thread
    const int bib  = warp * 2 + g;            // batch within block (0..7)
    const int batch = blockIdx.x * 8 + bib;   // global batch
    const float* xrow = x + (size_t)batch * 512;

    // ---- row j of W_hh in 16 scalar registers ----
    const float4 q0 = *(const float4*)(Whh + j * 16 + 0);
    const float4 q1 = *(const float4*)(Whh + j * 16 + 4);
    const float4 q2 = *(const float4*)(Whh + j * 16 + 8);
    const float4 q3 = *(const float4*)(Whh + j * 16 + 12);
    const float w0 = q0.x, w1 = q0.y, w2 = q0.z, w3 = q0.w;
    const float w4 = q1.x, w5 = q1.y, w6 = q1.z, w7 = q1.w;
    const float w8 = q2.x, w9 = q2.y, w10 = q2.z, w11 = q2.w;
    const float w12 = q3.x, w13 = q3.y, w14 = q3.z, w15 = q3.w;
    const float wihj = Wih[j];
    const float bj   = bih[j] + bhh[j];

    float hcur = 0.0f;   // h0 = 0

    // ---- x quad prefetch pipeline (4 steps per float4, depth 2) ----
    float4 cur = *(const float4*)(xrow + 0);
    float4 nxt = *(const float4*)(xrow + 4);

#define SH(K) __shfl_sync(0xffffffffu, hcur, (K), 16)

    // Shuffle-exchange + scalar dot. Shfl issue order k0..k15 matches the
    // 4-chain round-robin consumption (chain heads k0..k3 first).
#define DOT_Z(QX, ZOUT)                                                 \
        float k0  = SH(0),  k1  = SH(1),  k2  = SH(2),  k3  = SH(3);    \
        float k4  = SH(4),  k5  = SH(5),  k6  = SH(6),  k7  = SH(7);    \
        float k8  = SH(8),  k9  = SH(9),  k10 = SH(10), k11 = SH(11);   \
        float k12 = SH(12), k13 = SH(13), k14 = SH(14), k15 = SH(15);   \
        float a0 = fmaf(k0, w0, (QX));                                  \
        float a1 = k1 * w1;                                             \
        float a2 = k2 * w2;                                             \
        float a3 = k3 * w3;                                             \
        a0 = fmaf(k4,  w4,  a0);                                        \
        a1 = fmaf(k5,  w5,  a1);                                        \
        a2 = fmaf(k6,  w6,  a2);                                        \
        a3 = fmaf(k7,  w7,  a3);                                        \
        a0 = fmaf(k8,  w8,  a0);                                        \
        a1 = fmaf(k9,  w9,  a1);                                        \
        a2 = fmaf(k10, w10, a2);                                        \
        a3 = fmaf(k11, w11, a3);                                        \
        a0 = fmaf(k12, w12, a0);                                        \
        a1 = fmaf(k13, w13, a1);                                        \
        a2 = fmaf(k14, w14, a2);                                        \
        a3 = fmaf(k15, w15, a3);                                        \
        float ZOUT = (a0 + a1) + (a2 + a3);

    // Fast step: h = tanh.approx(z)
#define STEP_FAST(QX)                                                   \
    do {                                                                \
        DOT_Z(QX, z)                                                    \
        asm("tanh.approx.f32 %0, %1;" : "=f"(hcur) : "f"(z));           \
    } while (0)

    // Exact step: h = 1 - 2/(ex2(2*log2e*z)+1)
#define STEP_EXACT(QX)                                                  \
    do {                                                                \
        DOT_Z(QX, z)                                                    \
        float q = z * TWO_LOG2E;                                        \
        float e;                                                        \
        asm("ex2.approx.f32 %0, %1;" : "=f"(e) : "f"(q));               \
        float dd = e + 1.0f;                                            \
        float r;                                                        \
        asm("rcp.approx.f32 %0, %1;" : "=f"(r) : "f"(dd));              \
        hcur = fmaf(-2.0f, r, 1.0f);                                    \
    } while (0)

    // ---- phase 1: steps 0..447 fast (112 quads) ----
#pragma unroll 2
    for (int t4 = 0; t4 < 112; ++t4) {
        const int nidx = t4 + 2;  // max 113 < 128
        float4 tmp = *(const float4*)(xrow + nidx * 4);
        float qx0 = fmaf(cur.x, wihj, bj);
        float qx1 = fmaf(cur.y, wihj, bj);
        float qx2 = fmaf(cur.z, wihj, bj);
        float qx3 = fmaf(cur.w, wihj, bj);
        STEP_FAST(qx0);
        STEP_FAST(qx1);
        STEP_FAST(qx2);
        STEP_FAST(qx3);
        cur = nxt;
        nxt = tmp;
    }

    // ---- phase 2: steps 448..511 exact (16 quads) ----
#pragma unroll 2
    for (int t4 = 112; t4 < 128; ++t4) {
        const int nidx = (t4 + 2 < 128) ? (t4 + 2) : 127;
        float4 tmp = *(const float4*)(xrow + nidx * 4);
        float qx0 = fmaf(cur.x, wihj, bj);
        float qx1 = fmaf(cur.y, wihj, bj);
        float qx2 = fmaf(cur.z, wihj, bj);
        float qx3 = fmaf(cur.w, wihj, bj);
        STEP_EXACT(qx0);
        STEP_EXACT(qx1);
        STEP_EXACT(qx2);
        STEP_EXACT(qx3);
        cur = nxt;
        nxt = tmp;
    }
#undef STEP_FAST
#undef STEP_EXACT
#undef DOT_Z
#undef SH

    // ---- epilogue: out[b] = sum_j h_j * Wfc[j] + bfc ----
    float v = hcur * Wfc[j];
#pragma unroll
    for (int msk = 8; msk >= 1; msk >>= 1)
        v += __shfl_xor_sync(0xffffffffu, v, msk);
    if (j == 0)
        out[batch] = v + bfc[0];
}

extern "C" void kernel_launch(void* const* d_in, const int* in_sizes, int n_in,
                              void* d_out, int out_size) {
    const float* x   = (const float*)d_in[0];
    const float* Wih = (const float*)d_in[1];
    const float* Whh = (const float*)d_in[2];
    const float* bih = (const float*)d_in[3];
    const float* bhh = (const float*)d_in[4];
    const float* Wfc = (const float*)d_in[5];
    const float* bfc = (const float*)d_in[6];
    float* out = (float*)d_out;

    rnn_kernel<<<512, 128>>>(x, Wih, Whh, bih, bhh, Wfc, bfc, out);
}

// round 8
// speedup vs baseline: 1.4031x; 1.4031x over previous
#include <cuda_runtime.h>

// RNN_26938034880941: vanilla tanh RNN  B=4096, S=512, I=1, H=16, O=1
// Round 8: 2 chains per 16-lane group with CROSS-CHAIN LATENCY HIDING.
//   Unlike R5 (regression), each chain's LDS is issued right after its own
//   STS (producer side) and consumed half an iteration later — the other
//   chain's ~22-inst compute block covers the STS->LDS smem round-trip that
//   profiling showed dominates T_step. Volatile-asm order: STS_A < LDS_A <
//   STS_B < LDS_B each iteration.
//   16 lanes own units j for batches A,B; 4 batches/warp; grid 256 x 128.
//   Bank-exact smem (R5 layout, proven conflict-free): group region 128B,
//   rowA at +g*64, rowB at +(g^1)*64.
//   tanh.approx steps 0..447, exact ex2/rcp last 64. x via LDG.128 quads.

#define TWO_LOG2E 2.88539008177792681472f  // 2*log2(e)

__device__ __forceinline__ unsigned long long pack2(float a, float b) {
    unsigned long long r;
    asm("mov.b64 %0, {%1, %2};" : "=l"(r) : "f"(a), "f"(b));
    return r;
}
__device__ __forceinline__ unsigned long long fma2(unsigned long long a,
                                                   unsigned long long b,
                                                   unsigned long long c) {
    unsigned long long d;
    asm("fma.rn.f32x2 %0, %1, %2, %3;" : "=l"(d) : "l"(a), "l"(b), "l"(c));
    return d;
}
__device__ __forceinline__ unsigned long long add2(unsigned long long a,
                                                   unsigned long long b) {
    unsigned long long d;
    asm("add.rn.f32x2 %0, %1, %2;" : "=l"(d) : "l"(a), "l"(b));
    return d;
}
// Ordered smem ops (converged warp; in-warp LSU program order; memory clobber
// stops compiler reordering among volatile asm).
__device__ __forceinline__ void lds_v2u64(unsigned long long& a,
                                          unsigned long long& b, unsigned sa) {
    asm volatile("ld.shared.v2.b64 {%0, %1}, [%2];"
                 : "=l"(a), "=l"(b) : "r"(sa) : "memory");
}
__device__ __forceinline__ void sts_f32(unsigned sa, float v) {
    asm volatile("st.shared.f32 [%0], %1;" :: "r"(sa), "f"(v) : "memory");
}

__global__ void __launch_bounds__(128)
rnn_kernel(const float* __restrict__ x,     // [4096,512,1]
           const float* __restrict__ Wih,   // [16,1]
           const float* __restrict__ Whh,   // [16,16]
           const float* __restrict__ bih,   // [16]
           const float* __restrict__ bhh,   // [16]
           const float* __restrict__ Wfc,   // [1,16]
           const float* __restrict__ bfc,   // [1]
           float* __restrict__ out)         // [4096,1]
{
    // 8 groups per block, 128B region per group (rows A and B, 64B each).
    __shared__ __align__(128) float hbuf[8 * 32];

    const int tid  = threadIdx.x;
    const int lane = tid & 31;
    const int warp = tid >> 5;
    const int g    = lane >> 4;   // half-group within warp (0/1)
    const int j    = lane & 15;   // hidden unit owned by this thread
    const int gid  = warp * 2 + g;            // group in block (0..7)
    const int batchA = blockIdx.x * 16 + gid * 2;
    const int batchB = batchA + 1;
    const float* xrowA = x + (size_t)batchA * 512;
    const float* xrowB = x + (size_t)batchB * 512;

    // ---- shared weights: row j of W_hh packed into f32x2 pairs ----
    const float4 w0 = *(const float4*)(Whh + j * 16 + 0);
    const float4 w1 = *(const float4*)(Whh + j * 16 + 4);
    const float4 w2 = *(const float4*)(Whh + j * 16 + 8);
    const float4 w3 = *(const float4*)(Whh + j * 16 + 12);
    unsigned long long Wp[8];
    Wp[0] = pack2(w0.x, w0.y);  Wp[1] = pack2(w0.z, w0.w);
    Wp[2] = pack2(w1.x, w1.y);  Wp[3] = pack2(w1.z, w1.w);
    Wp[4] = pack2(w2.x, w2.y);  Wp[5] = pack2(w2.z, w2.w);
    Wp[6] = pack2(w3.x, w3.y);  Wp[7] = pack2(w3.z, w3.w);
    const float wihj = Wih[j];
    const float bj   = bih[j] + bhh[j];

    // ---- bank-exact row addresses ----
    const unsigned smem0 = (unsigned)__cvta_generic_to_shared(hbuf);
    const unsigned base  = smem0 + (unsigned)(gid * 128);
    const unsigned rowA  = base + (unsigned)(g << 6);
    const unsigned rowB  = base + (unsigned)((g ^ 1) << 6);
    const unsigned stA   = rowA + (unsigned)(j * 4);
    const unsigned stB   = rowB + (unsigned)(j * 4);

    // ---- h0 = 0; prime the h-register sets ----
    sts_f32(stA, 0.0f);
    sts_f32(stB, 0.0f);
    __syncwarp();   // one-time ordering of init stores

    unsigned long long A0, A1, A2, A3, A4, A5, A6, A7;
    unsigned long long B0, B1, B2, B3, B4, B5, B6, B7;
    lds_v2u64(A0, A1, rowA + 0);
    lds_v2u64(A2, A3, rowA + 16);
    lds_v2u64(A4, A5, rowA + 32);
    lds_v2u64(A6, A7, rowA + 48);
    lds_v2u64(B0, B1, rowB + 0);
    lds_v2u64(B2, B3, rowB + 16);
    lds_v2u64(B4, B5, rowB + 32);
    lds_v2u64(B6, B7, rowB + 48);

    float hA = 0.0f, hB = 0.0f;

    // ---- x quad prefetch (4 steps per float4, depth 2, both chains) ----
    float4 curA = *(const float4*)(xrowA + 0);
    float4 curB = *(const float4*)(xrowB + 0);
    float4 nxtA = *(const float4*)(xrowA + 4);
    float4 nxtB = *(const float4*)(xrowB + 4);

    // Half-step for one chain: consume prefetched h regs, produce new h,
    // store it, and immediately issue the LDS for the NEXT step (so the
    // other chain's block covers the smem round-trip).
#define HALF(R0,R1,R2,R3,R4,R5,R6,R7, ROW, ST, H, QX, FAST)            \
    do {                                                                \
        unsigned long long qxp = pack2((QX), 0.0f);                     \
        unsigned long long a0 = fma2(R0, Wp[0], qxp);                   \
        unsigned long long a1 = mul2_(R1, Wp[1]);                       \
        a0 = fma2(R2, Wp[2], a0);                                       \
        a1 = fma2(R3, Wp[3], a1);                                       \
        a0 = fma2(R4, Wp[4], a0);                                       \
        a1 = fma2(R5, Wp[5], a1);                                       \
        a0 = fma2(R6, Wp[6], a0);                                       \
        a1 = fma2(R7, Wp[7], a1);                                       \
        a0 = add2(a0, a1);                                              \
        float zlo, zhi;                                                 \
        asm("mov.b64 {%0, %1}, %2;" : "=f"(zlo), "=f"(zhi) : "l"(a0));  \
        float z = zlo + zhi;                                            \
        if (FAST) {                                                     \
            asm("tanh.approx.f32 %0, %1;" : "=f"(H) : "f"(z));          \
        } else {                                                        \
            float q = z * TWO_LOG2E;                                    \
            float e;                                                    \
            asm("ex2.approx.f32 %0, %1;" : "=f"(e) : "f"(q));           \
            float dd = e + 1.0f;                                        \
            float r;                                                    \
            asm("rcp.approx.f32 %0, %1;" : "=f"(r) : "f"(dd));          \
            H = fmaf(-2.0f, r, 1.0f);                                   \
        }                                                               \
        sts_f32(ST, H);                                                 \
        lds_v2u64(R0, R1, ROW + 0);                                     \
        lds_v2u64(R2, R3, ROW + 16);                                    \
        lds_v2u64(R4, R5, ROW + 32);                                    \
        lds_v2u64(R6, R7, ROW + 48);                                    \
    } while (0)

#define mul2_(A, B) ({                                                  \
        unsigned long long _d;                                          \
        asm("mul.rn.f32x2 %0, %1, %2;" : "=l"(_d) : "l"(A), "l"(B));    \
        _d; })

#define MACRO_STEP(QXA, QXB, FAST)                                      \
    do {                                                                \
        HALF(A0,A1,A2,A3,A4,A5,A6,A7, rowA, stA, hA, QXA, FAST);        \
        HALF(B0,B1,B2,B3,B4,B5,B6,B7, rowB, stB, hB, QXB, FAST);        \
    } while (0)

    // ---- phase 1: steps 0..447 fast (112 quads) ----
#pragma unroll 2
    for (int t4 = 0; t4 < 112; ++t4) {
        const int nidx = t4 + 2;  // max 113 < 128
        float4 tmpA = *(const float4*)(xrowA + nidx * 4);
        float4 tmpB = *(const float4*)(xrowB + nidx * 4);
        float qA0 = fmaf(curA.x, wihj, bj), qB0 = fmaf(curB.x, wihj, bj);
        float qA1 = fmaf(curA.y, wihj, bj), qB1 = fmaf(curB.y, wihj, bj);
        float qA2 = fmaf(curA.z, wihj, bj), qB2 = fmaf(curB.z, wihj, bj);
        float qA3 = fmaf(curA.w, wihj, bj), qB3 = fmaf(curB.w, wihj, bj);
        MACRO_STEP(qA0, qB0, 1);
        MACRO_STEP(qA1, qB1, 1);
        MACRO_STEP(qA2, qB2, 1);
        MACRO_STEP(qA3, qB3, 1);
        curA = nxtA;  nxtA = tmpA;
        curB = nxtB;  nxtB = tmpB;
    }

    // ---- phase 2: steps 448..511 exact (16 quads) ----
#pragma unroll 2
    for (int t4 = 112; t4 < 128; ++t4) {
        const int nidx = (t4 + 2 < 128) ? (t4 + 2) : 127;
        float4 tmpA = *(const float4*)(xrowA + nidx * 4);
        float4 tmpB = *(const float4*)(xrowB + nidx * 4);
        float qA0 = fmaf(curA.x, wihj, bj), qB0 = fmaf(curB.x, wihj, bj);
        float qA1 = fmaf(curA.y, wihj, bj), qB1 = fmaf(curB.y, wihj, bj);
        float qA2 = fmaf(curA.z, wihj, bj), qB2 = fmaf(curB.z, wihj, bj);
        float qA3 = fmaf(curA.w, wihj, bj), qB3 = fmaf(curB.w, wihj, bj);
        MACRO_STEP(qA0, qB0, 0);
        MACRO_STEP(qA1, qB1, 0);
        MACRO_STEP(qA2, qB2, 0);
        MACRO_STEP(qA3, qB3, 0);
        curA = nxtA;  nxtA = tmpA;
        curB = nxtB;  nxtB = tmpB;
    }
#undef MACRO_STEP
#undef HALF
#undef mul2_

    // ---- epilogue: out[b] = sum_j h_j * Wfc[j] + bfc, both chains ----
    const float wfcj = Wfc[j];
    float vA = hA * wfcj;
    float vB = hB * wfcj;
#pragma unroll
    for (int msk = 8; msk >= 1; msk >>= 1) {
        vA += __shfl_xor_sync(0xffffffffu, vA, msk);
        vB += __shfl_xor_sync(0xffffffffu, vB, msk);
    }
    if (j == 0) {
        const float bias = bfc[0];
        out[batchA] = vA + bias;
        out[batchB] = vB + bias;
    }
}

extern "C" void kernel_launch(void* const* d_in, const int* in_sizes, int n_in,
                              void* d_out, int out_size) {
    const float* x   = (const float*)d_in[0];
    const float* Wih = (const float*)d_in[1];
    const float* Whh = (const float*)d_in[2];
    const float* bih = (const float*)d_in[3];
    const float* bhh = (const float*)d_in[4];
    const float* Wfc = (const float*)d_in[5];
    const float* bfc = (const float*)d_in[6];
    float* out = (float*)d_out;

    // 4096 batches / 16 per block = 256 blocks, 128 threads each
    rnn_kernel<<<256, 128>>>(x, Wih, Whh, bih, bhh, Wfc, bfc, out);
}

// round 9
// speedup vs baseline: 1.4039x; 1.0006x over previous
#include <cuda_runtime.h>

// RNN_26938034880941: vanilla tanh RNN  B=4096, S=512, I=1, H=16, O=1
// Round 9: 4 interleaved chains per 16-lane group, producer-hoisted LDS.
//   R8 showed marginal chain cost ~29cyc with LDS issued right after STS
//   (round trip covered by other chains' compute). Amortize over 4 chains.
//   Grid 128 x 128: exactly <=1 CTA/SM -> 1 warp/SMSP, zero arbitration.
//   Bank-exact smem: 256B group region, row slot = chain^g so the warp's two
//   half-groups always access opposite 64B bank halves.
//   tanh.approx steps 0..447, exact ex2/rcp last 64. x via LDG.128 quads.

#define TWO_LOG2E 2.88539008177792681472f  // 2*log2(e)

__device__ __forceinline__ unsigned long long pack2(float a, float b) {
    unsigned long long r;
    asm("mov.b64 %0, {%1, %2};" : "=l"(r) : "f"(a), "f"(b));
    return r;
}
__device__ __forceinline__ unsigned long long fma2(unsigned long long a,
                                                   unsigned long long b,
                                                   unsigned long long c) {
    unsigned long long d;
    asm("fma.rn.f32x2 %0, %1, %2, %3;" : "=l"(d) : "l"(a), "l"(b), "l"(c));
    return d;
}
__device__ __forceinline__ unsigned long long add2(unsigned long long a,
                                                   unsigned long long b) {
    unsigned long long d;
    asm("add.rn.f32x2 %0, %1, %2;" : "=l"(d) : "l"(a), "l"(b));
    return d;
}
// Ordered smem ops (converged warp; in-warp LSU program order; memory clobber
// stops compiler reordering among volatile asm).
__device__ __forceinline__ void lds_v2u64(unsigned long long& a,
                                          unsigned long long& b, unsigned sa) {
    asm volatile("ld.shared.v2.b64 {%0, %1}, [%2];"
                 : "=l"(a), "=l"(b) : "r"(sa) : "memory");
}
__device__ __forceinline__ void sts_f32(unsigned sa, float v) {
    asm volatile("st.shared.f32 [%0], %1;" :: "r"(sa), "f"(v) : "memory");
}

__global__ void __launch_bounds__(128)
rnn_kernel(const float* __restrict__ x,     // [4096,512,1]
           const float* __restrict__ Wih,   // [16,1]
           const float* __restrict__ Whh,   // [16,16]
           const float* __restrict__ bih,   // [16]
           const float* __restrict__ bhh,   // [16]
           const float* __restrict__ Wfc,   // [1,16]
           const float* __restrict__ bfc,   // [1]
           float* __restrict__ out)         // [4096,1]
{
    // 8 groups per block, 256B region per group (4 rows of 64B).
    __shared__ __align__(128) float hbuf[8 * 64];

    const int tid  = threadIdx.x;
    const int lane = tid & 31;
    const int warp = tid >> 5;
    const int g    = lane >> 4;   // half-group within warp (0/1)
    const int j    = lane & 15;   // hidden unit owned by this thread
    const int gid  = warp * 2 + g;            // group in block (0..7)
    const int batch0 = blockIdx.x * 32 + gid * 4;   // 4 consecutive batches
    const float* xrow0 = x + (size_t)(batch0 + 0) * 512;
    const float* xrow1 = x + (size_t)(batch0 + 1) * 512;
    const float* xrow2 = x + (size_t)(batch0 + 2) * 512;
    const float* xrow3 = x + (size_t)(batch0 + 3) * 512;

    // ---- shared weights: row j of W_hh packed into f32x2 pairs ----
    const float4 w0 = *(const float4*)(Whh + j * 16 + 0);
    const float4 w1 = *(const float4*)(Whh + j * 16 + 4);
    const float4 w2 = *(const float4*)(Whh + j * 16 + 8);
    const float4 w3 = *(const float4*)(Whh + j * 16 + 12);
    unsigned long long Wp[8];
    Wp[0] = pack2(w0.x, w0.y);  Wp[1] = pack2(w0.z, w0.w);
    Wp[2] = pack2(w1.x, w1.y);  Wp[3] = pack2(w1.z, w1.w);
    Wp[4] = pack2(w2.x, w2.y);  Wp[5] = pack2(w2.z, w2.w);
    Wp[6] = pack2(w3.x, w3.y);  Wp[7] = pack2(w3.z, w3.w);
    const float wihj = Wih[j];
    const float bj   = bih[j] + bhh[j];

    // ---- bank-exact row addresses: slot = chain ^ g ----
    const unsigned smem0 = (unsigned)__cvta_generic_to_shared(hbuf);
    const unsigned base  = smem0 + (unsigned)(gid * 256);
    const unsigned rowA  = base + (unsigned)(((0 ^ g) & 3) << 6);
    const unsigned rowB  = base + (unsigned)(((1 ^ g) & 3) << 6);
    const unsigned rowC  = base + (unsigned)(((2 ^ g) & 3) << 6);
    const unsigned rowD  = base + (unsigned)(((3 ^ g) & 3) << 6);
    const unsigned stA = rowA + (unsigned)(j * 4);
    const unsigned stB = rowB + (unsigned)(j * 4);
    const unsigned stC = rowC + (unsigned)(j * 4);
    const unsigned stD = rowD + (unsigned)(j * 4);

    // ---- h0 = 0; prime all h-register sets ----
    sts_f32(stA, 0.0f);
    sts_f32(stB, 0.0f);
    sts_f32(stC, 0.0f);
    sts_f32(stD, 0.0f);
    __syncwarp();   // one-time ordering of init stores

    unsigned long long A0,A1,A2,A3,A4,A5,A6,A7;
    unsigned long long B0,B1,B2,B3,B4,B5,B6,B7;
    unsigned long long C0,C1,C2,C3,C4,C5,C6,C7;
    unsigned long long D0,D1,D2,D3,D4,D5,D6,D7;
    lds_v2u64(A0, A1, rowA + 0);  lds_v2u64(A2, A3, rowA + 16);
    lds_v2u64(A4, A5, rowA + 32); lds_v2u64(A6, A7, rowA + 48);
    lds_v2u64(B0, B1, rowB + 0);  lds_v2u64(B2, B3, rowB + 16);
    lds_v2u64(B4, B5, rowB + 32); lds_v2u64(B6, B7, rowB + 48);
    lds_v2u64(C0, C1, rowC + 0);  lds_v2u64(C2, C3, rowC + 16);
    lds_v2u64(C4, C5, rowC + 32); lds_v2u64(C6, C7, rowC + 48);
    lds_v2u64(D0, D1, rowD + 0);  lds_v2u64(D2, D3, rowD + 16);
    lds_v2u64(D4, D5, rowD + 32); lds_v2u64(D6, D7, rowD + 48);

    float hA = 0.0f, hB = 0.0f, hC = 0.0f, hD = 0.0f;

    // ---- x quad prefetch (4 steps per float4, depth 2, four chains) ----
    float4 curA = *(const float4*)(xrow0 + 0), nxtA = *(const float4*)(xrow0 + 4);
    float4 curB = *(const float4*)(xrow1 + 0), nxtB = *(const float4*)(xrow1 + 4);
    float4 curC = *(const float4*)(xrow2 + 0), nxtC = *(const float4*)(xrow2 + 4);
    float4 curD = *(const float4*)(xrow3 + 0), nxtD = *(const float4*)(xrow3 + 4);

#define mul2_(A, B) ({                                                  \
        unsigned long long _d;                                          \
        asm("mul.rn.f32x2 %0, %1, %2;" : "=l"(_d) : "l"(A), "l"(B));    \
        _d; })

    // Half-step for one chain: consume prefetched h regs, produce new h,
    // store it, then immediately issue the LDS for the NEXT step (round
    // trip covered by the other three chains' compute).
#define HALF(R0,R1,R2,R3,R4,R5,R6,R7, ROW, ST, H, QX, FAST)            \
    do {                                                                \
        unsigned long long qxp = pack2((QX), 0.0f);                     \
        unsigned long long a0 = fma2(R0, Wp[0], qxp);                   \
        unsigned long long a1 = mul2_(R1, Wp[1]);                       \
        a0 = fma2(R2, Wp[2], a0);                                       \
        a1 = fma2(R3, Wp[3], a1);                                       \
        a0 = fma2(R4, Wp[4], a0);                                       \
        a1 = fma2(R5, Wp[5], a1);                                       \
        a0 = fma2(R6, Wp[6], a0);                                       \
        a1 = fma2(R7, Wp[7], a1);                                       \
        a0 = add2(a0, a1);                                              \
        float zlo, zhi;                                                 \
        asm("mov.b64 {%0, %1}, %2;" : "=f"(zlo), "=f"(zhi) : "l"(a0));  \
        float z = zlo + zhi;                                            \
        if (FAST) {                                                     \
            asm("tanh.approx.f32 %0, %1;" : "=f"(H) : "f"(z));          \
        } else {                                                        \
            float q = z * TWO_LOG2E;                                    \
            float e;                                                    \
            asm("ex2.approx.f32 %0, %1;" : "=f"(e) : "f"(q));           \
            float dd = e + 1.0f;                                        \
            float r;                                                    \
            asm("rcp.approx.f32 %0, %1;" : "=f"(r) : "f"(dd));          \
            H = fmaf(-2.0f, r, 1.0f);                                   \
        }                                                               \
        sts_f32(ST, H);                                                 \
        lds_v2u64(R0, R1, ROW + 0);                                     \
        lds_v2u64(R2, R3, ROW + 16);                                    \
        lds_v2u64(R4, R5, ROW + 32);                                    \
        lds_v2u64(R6, R7, ROW + 48);                                    \
    } while (0)

#define MACRO_STEP(QA, QB, QC, QD, FAST)                                \
    do {                                                                \
        HALF(A0,A1,A2,A3,A4,A5,A6,A7, rowA, stA, hA, QA, FAST);         \
        HALF(B0,B1,B2,B3,B4,B5,B6,B7, rowB, stB, hB, QB, FAST);         \
        HALF(C0,C1,C2,C3,C4,C5,C6,C7, rowC, stC, hC, QC, FAST);         \
        HALF(D0,D1,D2,D3,D4,D5,D6,D7, rowD, stD, hD, QD, FAST);         \
    } while (0)

    // ---- phase 1: steps 0..447 fast (112 quads) ----
#pragma unroll 1
    for (int t4 = 0; t4 < 112; ++t4) {
        const int nidx = t4 + 2;  // max 113 < 128
        float4 tmpA = *(const float4*)(xrow0 + nidx * 4);
        float4 tmpB = *(const float4*)(xrow1 + nidx * 4);
        float4 tmpC = *(const float4*)(xrow2 + nidx * 4);
        float4 tmpD = *(const float4*)(xrow3 + nidx * 4);
        float qA0 = fmaf(curA.x, wihj, bj), qB0 = fmaf(curB.x, wihj, bj);
        float qC0 = fmaf(curC.x, wihj, bj), qD0 = fmaf(curD.x, wihj, bj);
        float qA1 = fmaf(curA.y, wihj, bj), qB1 = fmaf(curB.y, wihj, bj);
        float qC1 = fmaf(curC.y, wihj, bj), qD1 = fmaf(curD.y, wihj, bj);
        float qA2 = fmaf(curA.z, wihj, bj), qB2 = fmaf(curB.z, wihj, bj);
        float qC2 = fmaf(curC.z, wihj, bj), qD2 = fmaf(curD.z, wihj, bj);
        float qA3 = fmaf(curA.w, wihj, bj), qB3 = fmaf(curB.w, wihj, bj);
        float qC3 = fmaf(curC.w, wihj, bj), qD3 = fmaf(curD.w, wihj, bj);
        MACRO_STEP(qA0, qB0, qC0, qD0, 1);
        MACRO_STEP(qA1, qB1, qC1, qD1, 1);
        MACRO_STEP(qA2, qB2, qC2, qD2, 1);
        MACRO_STEP(qA3, qB3, qC3, qD3, 1);
        curA = nxtA;  nxtA = tmpA;
        curB = nxtB;  nxtB = tmpB;
        curC = nxtC;  nxtC = tmpC;
        curD = nxtD;  nxtD = tmpD;
    }

    // ---- phase 2: steps 448..511 exact (16 quads) ----
#pragma unroll 1
    for (int t4 = 112; t4 < 128; ++t4) {
        const int nidx = (t4 + 2 < 128) ? (t4 + 2) : 127;
        float4 tmpA = *(const float4*)(xrow0 + nidx * 4);
        float4 tmpB = *(const float4*)(xrow1 + nidx * 4);
        float4 tmpC = *(const float4*)(xrow2 + nidx * 4);
        float4 tmpD = *(const float4*)(xrow3 + nidx * 4);
        float qA0 = fmaf(curA.x, wihj, bj), qB0 = fmaf(curB.x, wihj, bj);
        float qC0 = fmaf(curC.x, wihj, bj), qD0 = fmaf(curD.x, wihj, bj);
        float qA1 = fmaf(curA.y, wihj, bj), qB1 = fmaf(curB.y, wihj, bj);
        float qC1 = fmaf(curC.y, wihj, bj), qD1 = fmaf(curD.y, wihj, bj);
        float qA2 = fmaf(curA.z, wihj, bj), qB2 = fmaf(curB.z, wihj, bj);
        float qC2 = fmaf(curC.z, wihj, bj), qD2 = fmaf(curD.z, wihj, bj);
        float qA3 = fmaf(curA.w, wihj, bj), qB3 = fmaf(curB.w, wihj, bj);
        float qC3 = fmaf(curC.w, wihj, bj), qD3 = fmaf(curD.w, wihj, bj);
        MACRO_STEP(qA0, qB0, qC0, qD0, 0);
        MACRO_STEP(qA1, qB1, qC1, qD1, 0);
        MACRO_STEP(qA2, qB2, qC2, qD2, 0);
        MACRO_STEP(qA3, qB3, qC3, qD3, 0);
        curA = nxtA;  nxtA = tmpA;
        curB = nxtB;  nxtB = tmpB;
        curC = nxtC;  nxtC = tmpC;
        curD = nxtD;  nxtD = tmpD;
    }
#undef MACRO_STEP
#undef HALF
#undef mul2_

    // ---- epilogue: out[b] = sum_j h_j * Wfc[j] + bfc, four chains ----
    const float wfcj = Wfc[j];
    float vA = hA * wfcj;
    float vB = hB * wfcj;
    float vC = hC * wfcj;
    float vD = hD * wfcj;
#pragma unroll
    for (int msk = 8; msk >= 1; msk >>= 1) {
        vA += __shfl_xor_sync(0xffffffffu, vA, msk);
        vB += __shfl_xor_sync(0xffffffffu, vB, msk);
        vC += __shfl_xor_sync(0xffffffffu, vC, msk);
        vD += __shfl_xor_sync(0xffffffffu, vD, msk);
    }
    if (j == 0) {
        const float bias = bfc[0];
        out[batch0 + 0] = vA + bias;
        out[batch0 + 1] = vB + bias;
        out[batch0 + 2] = vC + bias;
        out[batch0 + 3] = vD + bias;
    }
}

extern "C" void kernel_launch(void* const* d_in, const int* in_sizes, int n_in,
                              void* d_out, int out_size) {
    const float* x   = (const float*)d_in[0];
    const float* Wih = (const float*)d_in[1];
    const float* Whh = (const float*)d_in[2];
    const float* bih = (const float*)d_in[3];
    const float* bhh = (const float*)d_in[4];
    const float* Wfc = (const float*)d_in[5];
    const float* bfc = (const float*)d_in[6];
    float* out = (float*)d_out;

    // 4096 batches / 32 per block = 128 blocks, 128 threads each
    // (<=1 CTA/SM: one warp per SMSP, zero arbitration interference)
    rnn_kernel<<<128, 128>>>(x, Wih, Whh, bih, bhh, Wfc, bfc, out);
}

// round 10
// speedup vs baseline: 1.7993x; 1.2816x over previous
#include <cuda_runtime.h>
#include <cuda_fp16.h>

// RNN_26938034880941: vanilla tanh RNN  B=4096, S=512, I=1, H=16, O=1
// Round 10: fp16 arithmetic for the contracting phase.
//   R4 proved per-step errors ~5e-4 injected before the last 64 steps decay
//   below 1e-7 at the output. fp16 rounding is the same magnitude, so:
//   steps 0..447: HFMA2 dot (half fma-pipe cost), h exchanged as 16 halves
//   (32B -> 2 LDS.128), tanh.approx.f16.
//   step 448: transition (read fp16 h, exact fp32 math, store fp32 row).
//   steps 449..511: exact fp32 path (f32x2 dot + ex2/rcp tanh).
// Mapping: R6 (best): 16 lanes/batch, 2 batches/warp, 512 blocks x 128.

#define TWO_LOG2E 2.88539008177792681472f  // 2*log2(e)

__device__ __forceinline__ unsigned long long pack2(float a, float b) {
    unsigned long long r;
    asm("mov.b64 %0, {%1, %2};" : "=l"(r) : "f"(a), "f"(b));
    return r;
}
__device__ __forceinline__ unsigned long long fma2(unsigned long long a,
                                                   unsigned long long b,
                                                   unsigned long long c) {
    unsigned long long d;
    asm("fma.rn.f32x2 %0, %1, %2, %3;" : "=l"(d) : "l"(a), "l"(b), "l"(c));
    return d;
}
__device__ __forceinline__ unsigned long long mul2u(unsigned long long a,
                                                    unsigned long long b) {
    unsigned long long d;
    asm("mul.rn.f32x2 %0, %1, %2;" : "=l"(d) : "l"(a), "l"(b));
    return d;
}
__device__ __forceinline__ unsigned long long add2(unsigned long long a,
                                                   unsigned long long b) {
    unsigned long long d;
    asm("add.rn.f32x2 %0, %1, %2;" : "=l"(d) : "l"(a), "l"(b));
    return d;
}
// Ordered smem ops (converged warp; in-warp LSU program order; memory clobber
// stops compiler reordering among volatile asm).
__device__ __forceinline__ void lds_v2u64(unsigned long long& a,
                                          unsigned long long& b, unsigned sa) {
    asm volatile("ld.shared.v2.b64 {%0, %1}, [%2];"
                 : "=l"(a), "=l"(b) : "r"(sa) : "memory");
}
__device__ __forceinline__ void lds_v4b32(uint4& v, unsigned sa) {
    asm volatile("ld.shared.v4.b32 {%0, %1, %2, %3}, [%4];"
                 : "=r"(v.x), "=r"(v.y), "=r"(v.z), "=r"(v.w)
                 : "r"(sa) : "memory");
}
__device__ __forceinline__ void sts_f32(unsigned sa, float v) {
    asm volatile("st.shared.f32 [%0], %1;" :: "r"(sa), "f"(v) : "memory");
}
__device__ __forceinline__ void sts_u16(unsigned sa, unsigned short v) {
    asm volatile("st.shared.u16 [%0], %1;" :: "r"(sa), "h"(v) : "memory");
}
__device__ __forceinline__ __half2 u2h(unsigned u) {
    __half2 h;
    *reinterpret_cast<unsigned*>(&h) = u;
    return h;
}

__global__ void __launch_bounds__(128)
rnn_kernel(const float* __restrict__ x,     // [4096,512,1]
           const float* __restrict__ Wih,   // [16,1]
           const float* __restrict__ Whh,   // [16,16]
           const float* __restrict__ bih,   // [16]
           const float* __restrict__ bhh,   // [16]
           const float* __restrict__ Wfc,   // [1,16]
           const float* __restrict__ bfc,   // [1]
           float* __restrict__ out)         // [4096,1]
{
    // 64B row stride for both buffers -> warp's two groups hit disjoint
    // bank halves (R6-proven layout). fp16 rows use only first 32B.
    __shared__ __align__(16) __half hbuf16[8][32];  // 64B rows
    __shared__ __align__(16) float  hbuf32[8][16];  // 64B rows

    const int tid  = threadIdx.x;
    const int lane = tid & 31;
    const int warp = tid >> 5;
    const int g    = lane >> 4;   // group within warp (0/1)
    const int j    = lane & 15;   // hidden unit owned by this thread
    const int bib  = warp * 2 + g;            // batch within block (0..7)
    const int batch = blockIdx.x * 8 + bib;   // global batch
    const float* xrow = x + (size_t)batch * 512;

    // ---- weights: row j of W_hh, packed both f32x2 and f16x2 ----
    const float4 w0 = *(const float4*)(Whh + j * 16 + 0);
    const float4 w1 = *(const float4*)(Whh + j * 16 + 4);
    const float4 w2 = *(const float4*)(Whh + j * 16 + 8);
    const float4 w3 = *(const float4*)(Whh + j * 16 + 12);
    unsigned long long Wp[8];
    Wp[0] = pack2(w0.x, w0.y);  Wp[1] = pack2(w0.z, w0.w);
    Wp[2] = pack2(w1.x, w1.y);  Wp[3] = pack2(w1.z, w1.w);
    Wp[4] = pack2(w2.x, w2.y);  Wp[5] = pack2(w2.z, w2.w);
    Wp[6] = pack2(w3.x, w3.y);  Wp[7] = pack2(w3.z, w3.w);
    __half2 Wh[8];
    Wh[0] = __floats2half2_rn(w0.x, w0.y);  Wh[1] = __floats2half2_rn(w0.z, w0.w);
    Wh[2] = __floats2half2_rn(w1.x, w1.y);  Wh[3] = __floats2half2_rn(w1.z, w1.w);
    Wh[4] = __floats2half2_rn(w2.x, w2.y);  Wh[5] = __floats2half2_rn(w2.z, w2.w);
    Wh[6] = __floats2half2_rn(w3.x, w3.y);  Wh[7] = __floats2half2_rn(w3.z, w3.w);
    const float wihj = Wih[j];
    const float bj   = bih[j] + bhh[j];

    const unsigned row16 = (unsigned)__cvta_generic_to_shared(&hbuf16[bib][0]);
    const unsigned st16  = row16 + (unsigned)(j * 2);
    const unsigned row32 = (unsigned)__cvta_generic_to_shared(&hbuf32[bib][0]);
    const unsigned st32  = row32 + (unsigned)(j * 4);

    // ---- h0 = 0 (fp16 row feeds phase 1) ----
    sts_u16(st16, (unsigned short)0);
    __syncwarp();   // one-time: order init stores before first asm LDS

    float hcur = 0.0f;

    // ---- x quad prefetch pipeline (4 steps per float4, depth 2) ----
    float4 cur = *(const float4*)(xrow + 0);
    float4 nxt = *(const float4*)(xrow + 4);

    // Fast fp16 step: z = qxh + W_h . h16 ; h = tanh.approx.f16(z)
#define STEP_FAST16(QXH)                                                \
    do {                                                                \
        uint4 p0, p1;                                                   \
        lds_v4b32(p0, row16);                                           \
        lds_v4b32(p1, row16 + 16);                                      \
        __half2 a0 = __hfma2(u2h(p0.x), Wh[0], (QXH));                  \
        __half2 a1 = __hmul2(u2h(p0.y), Wh[1]);                         \
        a0 = __hfma2(u2h(p0.z), Wh[2], a0);                             \
        a1 = __hfma2(u2h(p0.w), Wh[3], a1);                             \
        a0 = __hfma2(u2h(p1.x), Wh[4], a0);                             \
        a1 = __hfma2(u2h(p1.y), Wh[5], a1);                             \
        a0 = __hfma2(u2h(p1.z), Wh[6], a0);                             \
        a1 = __hfma2(u2h(p1.w), Wh[7], a1);                             \
        a0 = __hadd2(a0, a1);                                           \
        __half zh = __hadd(__low2half(a0), __high2half(a0));            \
        unsigned short zr = __half_as_ushort(zh), hr;                   \
        asm("tanh.approx.f16 %0, %1;" : "=h"(hr) : "h"(zr));            \
        sts_u16(st16, hr);                                              \
    } while (0)

    // Exact fp32 dot core (reads packed f32x2 h regs h0..h7)
#define DOT32_TAIL(QX)                                                  \
        unsigned long long qxp = pack2((QX), 0.0f);                     \
        unsigned long long a0 = fma2(h0, Wp[0], qxp);                   \
        unsigned long long a1 = mul2u(h1, Wp[1]);                       \
        a0 = fma2(h2, Wp[2], a0);                                       \
        a1 = fma2(h3, Wp[3], a1);                                       \
        a0 = fma2(h4, Wp[4], a0);                                       \
        a1 = fma2(h5, Wp[5], a1);                                       \
        a0 = fma2(h6, Wp[6], a0);                                       \
        a1 = fma2(h7, Wp[7], a1);                                       \
        a0 = add2(a0, a1);                                              \
        float zlo, zhi;                                                 \
        asm("mov.b64 {%0, %1}, %2;" : "=f"(zlo), "=f"(zhi) : "l"(a0));  \
        float z = zlo + zhi;                                            \
        float q = z * TWO_LOG2E;                                        \
        float e;                                                        \
        asm("ex2.approx.f32 %0, %1;" : "=f"(e) : "f"(q));               \
        float dd = e + 1.0f;                                            \
        float r;                                                        \
        asm("rcp.approx.f32 %0, %1;" : "=f"(r) : "f"(dd));              \
        hcur = fmaf(-2.0f, r, 1.0f);                                    \
        sts_f32(st32, hcur);

    // Exact step reading fp32 row
#define STEP_EXACT(QX)                                                  \
    do {                                                                \
        unsigned long long h0, h1, h2, h3, h4, h5, h6, h7;              \
        lds_v2u64(h0, h1, row32 + 0);                                   \
        lds_v2u64(h2, h3, row32 + 16);                                  \
        lds_v2u64(h4, h5, row32 + 32);                                  \
        lds_v2u64(h6, h7, row32 + 48);                                  \
        DOT32_TAIL(QX)                                                  \
    } while (0)

    // Transition step: read fp16 row, exact fp32 math, store fp32 row
#define STEP_TRANS(QX)                                                  \
    do {                                                                \
        uint4 p0, p1;                                                   \
        lds_v4b32(p0, row16);                                           \
        lds_v4b32(p1, row16 + 16);                                      \
        float2 f0 = __half22float2(u2h(p0.x));                          \
        float2 f1 = __half22float2(u2h(p0.y));                          \
        float2 f2 = __half22float2(u2h(p0.z));                          \
        float2 f3 = __half22float2(u2h(p0.w));                          \
        float2 f4 = __half22float2(u2h(p1.x));                          \
        float2 f5 = __half22float2(u2h(p1.y));                          \
        float2 f6 = __half22float2(u2h(p1.z));                          \
        float2 f7 = __half22float2(u2h(p1.w));                          \
        unsigned long long h0 = pack2(f0.x, f0.y);                      \
        unsigned long long h1 = pack2(f1.x, f1.y);                      \
        unsigned long long h2 = pack2(f2.x, f2.y);                      \
        unsigned long long h3 = pack2(f3.x, f3.y);                      \
        unsigned long long h4 = pack2(f4.x, f4.y);                      \
        unsigned long long h5 = pack2(f5.x, f5.y);                      \
        unsigned long long h6 = pack2(f6.x, f6.y);                      \
        unsigned long long h7 = pack2(f7.x, f7.y);                      \
        DOT32_TAIL(QX)                                                  \
    } while (0)

    // ---- phase 1: steps 0..447 fast fp16 (112 quads) ----
#pragma unroll 2
    for (int t4 = 0; t4 < 112; ++t4) {
        const int nidx = t4 + 2;  // max 113 < 128
        float4 tmp = *(const float4*)(xrow + nidx * 4);
        __half2 q0 = __floats2half2_rn(fmaf(cur.x, wihj, bj), 0.0f);
        __half2 q1 = __floats2half2_rn(fmaf(cur.y, wihj, bj), 0.0f);
        __half2 q2 = __floats2half2_rn(fmaf(cur.z, wihj, bj), 0.0f);
        __half2 q3 = __floats2half2_rn(fmaf(cur.w, wihj, bj), 0.0f);
        STEP_FAST16(q0);
        STEP_FAST16(q1);
        STEP_FAST16(q2);
        STEP_FAST16(q3);
        cur = nxt;
        nxt = tmp;
    }

    // ---- transition quad (steps 448..451): trans + 3 exact ----
    {
        float4 tmp = *(const float4*)(xrow + 114 * 4);
        float qx0 = fmaf(cur.x, wihj, bj);
        float qx1 = fmaf(cur.y, wihj, bj);
        float qx2 = fmaf(cur.z, wihj, bj);
        float qx3 = fmaf(cur.w, wihj, bj);
        STEP_TRANS(qx0);
        STEP_EXACT(qx1);
        STEP_EXACT(qx2);
        STEP_EXACT(qx3);
        cur = nxt;
        nxt = tmp;
    }

    // ---- phase 2: steps 452..511 exact fp32 (15 quads) ----
#pragma unroll 2
    for (int t4 = 113; t4 < 128; ++t4) {
        const int nidx = (t4 + 2 < 128) ? (t4 + 2) : 127;
        float4 tmp = *(const float4*)(xrow + nidx * 4);
        float qx0 = fmaf(cur.x, wihj, bj);
        float qx1 = fmaf(cur.y, wihj, bj);
        float qx2 = fmaf(cur.z, wihj, bj);
        float qx3 = fmaf(cur.w, wihj, bj);
        STEP_EXACT(qx0);
        STEP_EXACT(qx1);
        STEP_EXACT(qx2);
        STEP_EXACT(qx3);
        cur = nxt;
        nxt = tmp;
    }
#undef STEP_FAST16
#undef STEP_EXACT
#undef STEP_TRANS
#undef DOT32_TAIL

    // ---- epilogue: out[b] = sum_j h_j * Wfc[j] + bfc ----
    float v = hcur * Wfc[j];
#pragma unroll
    for (int msk = 8; msk >= 1; msk >>= 1)
        v += __shfl_xor_sync(0xffffffffu, v, msk);
    if (j == 0)
        out[batch] = v + bfc[0];
}

extern "C" void kernel_launch(void* const* d_in, const int* in_sizes, int n_in,
                              void* d_out, int out_size) {
    const float* x   = (const float*)d_in[0];
    const float* Wih = (const float*)d_in[1];
    const float* Whh = (const float*)d_in[2];
    const float* bih = (const float*)d_in[3];
    const float* bhh = (const float*)d_in[4];
    const float* Wfc = (const float*)d_in[5];
    const float* bfc = (const float*)d_in[6];
    float* out = (float*)d_out;

    rnn_kernel<<<512, 128>>>(x, Wih, Whh, bih, bhh, Wfc, bfc, out);
}

// round 11
// speedup vs baseline: 1.9734x; 1.0968x over previous
#include <cuda_runtime.h>
#include <cuda_fp16.h>

// RNN_26938034880941: vanilla tanh RNN  B=4096, S=512, I=1, H=16, O=1
// Round 11: in-register MMA recurrence — NO memory ops in the fast loop.
//   One warp owns 8 batches. Step = mma.m16n8k16.f16 (A=W_hh const frag,
//   B=h frag, C=qx bias frag) -> tanh.approx.f16x2 -> movmatrix.m8n8.trans
//   (D fragment -> next B fragment; layouts verified to line up exactly).
//   Phase 1 (steps 0..447) fp16 (error decays: proven R4/R10).
//   Transition: h447 -> f32 smem rows (80B stride, conflict-free).
//   Tail (448..511): exact f32, 4 lanes/batch x 4 rows/lane, f32x2 + ex2/rcp.

#define TWO_LOG2E 2.88539008177792681472f  // 2*log2(e)

__device__ __forceinline__ unsigned long long pack2(float a, float b) {
    unsigned long long r;
    asm("mov.b64 %0, {%1, %2};" : "=l"(r) : "f"(a), "f"(b));
    return r;
}
__device__ __forceinline__ unsigned long long fma2(unsigned long long a,
                                                   unsigned long long b,
                                                   unsigned long long c) {
    unsigned long long d;
    asm("fma.rn.f32x2 %0, %1, %2, %3;" : "=l"(d) : "l"(a), "l"(b), "l"(c));
    return d;
}
__device__ __forceinline__ unsigned long long mul2(unsigned long long a,
                                                   unsigned long long b) {
    unsigned long long d;
    asm("mul.rn.f32x2 %0, %1, %2;" : "=l"(d) : "l"(a), "l"(b));
    return d;
}
__device__ __forceinline__ unsigned long long add2(unsigned long long a,
                                                   unsigned long long b) {
    unsigned long long d;
    asm("add.rn.f32x2 %0, %1, %2;" : "=l"(d) : "l"(a), "l"(b));
    return d;
}
__device__ __forceinline__ void lds_v2u64(unsigned long long& a,
                                          unsigned long long& b, unsigned sa) {
    asm volatile("ld.shared.v2.b64 {%0, %1}, [%2];"
                 : "=l"(a), "=l"(b) : "r"(sa) : "memory");
}
__device__ __forceinline__ void sts_f32(unsigned sa, float v) {
    asm volatile("st.shared.f32 [%0], %1;" :: "r"(sa), "f"(v) : "memory");
}
__device__ __forceinline__ void sts_v4f32(unsigned sa, float a, float b,
                                          float c, float d) {
    asm volatile("st.shared.v4.f32 [%0], {%1, %2, %3, %4};"
                 :: "r"(sa), "f"(a), "f"(b), "f"(c), "f"(d) : "memory");
}
// cvt.rn.f16x2.f32 d, a, b -> d.hi = cvt(a), d.lo = cvt(b)
__device__ __forceinline__ unsigned f16x2_pair(float lo, float hi) {
    unsigned r;
    asm("cvt.rn.f16x2.f32 %0, %1, %2;" : "=r"(r) : "f"(hi), "f"(lo));
    return r;
}

__global__ void __launch_bounds__(128)
rnn_kernel(const float* __restrict__ x,     // [4096,512,1]
           const float* __restrict__ Wih,   // [16,1]
           const float* __restrict__ Whh,   // [16,16]
           const float* __restrict__ bih,   // [16]
           const float* __restrict__ bhh,   // [16]
           const float* __restrict__ Wfc,   // [1,16]
           const float* __restrict__ bfc,   // [1]
           float* __restrict__ out)         // [4096,1]
{
    // Tail exchange buffer: per warp, 8 batch rows, 80B stride (20 floats)
    // -> every row starts on a distinct 4-bank group (20*bb mod 32 distinct).
    __shared__ __align__(16) float hbuf[4][8 * 20 + 4];

    const int tid  = threadIdx.x;
    const int lane = tid & 31;
    const int warp = tid >> 5;
    const int r    = lane >> 2;   // 0..7 : MMA row group / tail batch id
    const int m    = lane & 3;    // 0..3 : MMA col group / tail row group
    const int batch0 = blockIdx.x * 32 + warp * 8;

    // ==================== Phase 1: fp16 MMA recurrence ====================
    // A fragment (W_hh, row-major, f16): lane holds
    //   A0={W[r][2m],W[r][2m+1]}  A1={W[r+8][2m],...}
    //   A2={W[r][2m+8],...}       A3={W[r+8][2m+8],...}
    const float* Wr0 = Whh + r * 16;
    const float* Wr8 = Whh + (r + 8) * 16;
    const unsigned A0 = f16x2_pair(Wr0[2 * m],     Wr0[2 * m + 1]);
    const unsigned A1 = f16x2_pair(Wr8[2 * m],     Wr8[2 * m + 1]);
    const unsigned A2 = f16x2_pair(Wr0[2 * m + 8], Wr0[2 * m + 9]);
    const unsigned A3 = f16x2_pair(Wr8[2 * m + 8], Wr8[2 * m + 9]);

    const float wih_lo = Wih[r],      wih_hi = Wih[r + 8];
    const float bb_lo  = bih[r] + bhh[r];
    const float bb_hi  = bih[r + 8] + bhh[r + 8];

    // x streams for this lane's two columns (batches 2m, 2m+1 of the warp)
    const float* xr0 = x + (size_t)(batch0 + 2 * m) * 512;
    const float* xr1 = x + (size_t)(batch0 + 2 * m + 1) * 512;
    float4 cur0 = *(const float4*)(xr0),     nxt0 = *(const float4*)(xr0 + 4);
    float4 cur1 = *(const float4*)(xr1),     nxt1 = *(const float4*)(xr1 + 4);

    unsigned B0 = 0u, B1 = 0u;     // h0 = 0 (B fragment)
    unsigned D0h = 0u, D1h = 0u;   // post-tanh D fragment (h_t)

    // One step: z = W.h + qx (MMA, qx as accumulator), h = tanh(z),
    // D->B via two 8x8 transposes. No memory ops.
#define STEP_MMA(X0, X1)                                                \
    do {                                                                \
        float ql0 = fmaf((X0), wih_lo, bb_lo);                          \
        float ql1 = fmaf((X1), wih_lo, bb_lo);                          \
        float qh0 = fmaf((X0), wih_hi, bb_hi);                          \
        float qh1 = fmaf((X1), wih_hi, bb_hi);                          \
        unsigned C0 = f16x2_pair(ql0, ql1);                             \
        unsigned C1 = f16x2_pair(qh0, qh1);                             \
        unsigned D0, D1;                                                \
        asm("mma.sync.aligned.m16n8k16.row.col.f16.f16.f16.f16 "        \
            "{%0,%1}, {%2,%3,%4,%5}, {%6,%7}, {%8,%9};"                 \
            : "=r"(D0), "=r"(D1)                                        \
            : "r"(A0), "r"(A1), "r"(A2), "r"(A3),                       \
              "r"(B0), "r"(B1), "r"(C0), "r"(C1));                      \
        asm("tanh.approx.f16x2 %0, %1;" : "=r"(D0h) : "r"(D0));         \
        asm("tanh.approx.f16x2 %0, %1;" : "=r"(D1h) : "r"(D1));         \
        asm("movmatrix.sync.aligned.m8n8.trans.b16 %0, %1;"             \
            : "=r"(B0) : "r"(D0h));                                     \
        asm("movmatrix.sync.aligned.m8n8.trans.b16 %0, %1;"             \
            : "=r"(B1) : "r"(D1h));                                     \
    } while (0)

#pragma unroll 2
    for (int t4 = 0; t4 < 112; ++t4) {     // steps 0..447
        const int nidx = t4 + 2;           // max 113 < 128
        float4 tmp0 = *(const float4*)(xr0 + nidx * 4);
        float4 tmp1 = *(const float4*)(xr1 + nidx * 4);
        STEP_MMA(cur0.x, cur1.x);
        STEP_MMA(cur0.y, cur1.y);
        STEP_MMA(cur0.z, cur1.z);
        STEP_MMA(cur0.w, cur1.w);
        cur0 = nxt0;  nxt0 = tmp0;
        cur1 = nxt1;  nxt1 = tmp1;
    }
#undef STEP_MMA

    // ==================== Transition: h447 -> f32 smem ====================
    const unsigned sbase = (unsigned)__cvta_generic_to_shared(&hbuf[warp][0]);
    {
        __half2 lo2 = *reinterpret_cast<__half2*>(&D0h);  // (h[r][b0], h[r][b1])
        __half2 hi2 = *reinterpret_cast<__half2*>(&D1h);  // (h[r+8][b0], h[r+8][b1])
        float2 flo = __half22float2(lo2);
        float2 fhi = __half22float2(hi2);
        sts_f32(sbase + (unsigned)((2 * m)     * 80 + r * 4),       flo.x);
        sts_f32(sbase + (unsigned)((2 * m + 1) * 80 + r * 4),       flo.y);
        sts_f32(sbase + (unsigned)((2 * m)     * 80 + (r + 8) * 4), fhi.x);
        sts_f32(sbase + (unsigned)((2 * m + 1) * 80 + (r + 8) * 4), fhi.y);
    }
    __syncwarp();

    // ==================== Tail: 64 exact f32 steps ====================
    // Lane = (batch r, row group m): owns hidden units 4m..4m+3 of batch r.
    unsigned long long Wt0[8], Wt1[8], Wt2[8], Wt3[8];
    float qw0, qw1, qw2, qw3, qb0, qb1, qb2, qb3;
    {
        const float* w_a = Whh + (4 * m + 0) * 16;
        const float* w_b = Whh + (4 * m + 1) * 16;
        const float* w_c = Whh + (4 * m + 2) * 16;
        const float* w_d = Whh + (4 * m + 3) * 16;
#pragma unroll
        for (int k = 0; k < 8; ++k) {
            Wt0[k] = pack2(w_a[2 * k], w_a[2 * k + 1]);
            Wt1[k] = pack2(w_b[2 * k], w_b[2 * k + 1]);
            Wt2[k] = pack2(w_c[2 * k], w_c[2 * k + 1]);
            Wt3[k] = pack2(w_d[2 * k], w_d[2 * k + 1]);
        }
        qw0 = Wih[4 * m + 0];  qb0 = bih[4 * m + 0] + bhh[4 * m + 0];
        qw1 = Wih[4 * m + 1];  qb1 = bih[4 * m + 1] + bhh[4 * m + 1];
        qw2 = Wih[4 * m + 2];  qb2 = bih[4 * m + 2] + bhh[4 * m + 2];
        qw3 = Wih[4 * m + 3];  qb3 = bih[4 * m + 3] + bhh[4 * m + 3];
    }
    const unsigned rowb = sbase + (unsigned)(r * 80);
    const unsigned stb  = rowb + (unsigned)(m * 16);
    const float* xrt = x + (size_t)(batch0 + r) * 512 + 448;
    float4 curt = *(const float4*)(xrt);
    float4 nxtt = *(const float4*)(xrt + 4);

    float ha = 0.0f, hb = 0.0f, hc = 0.0f, hd = 0.0f;

    // One exact row: z = qx + W_row . h ; h = 1 - 2/(ex2(c*z)+1)
#define TAILROW(WT, QW, QB, XV, HOUT)                                   \
    do {                                                                \
        unsigned long long acc0 = fma2(h0, WT[0],                       \
                                       pack2(fmaf((XV), QW, QB), 0.f)); \
        unsigned long long acc1 = mul2(h1, WT[1]);                      \
        acc0 = fma2(h2, WT[2], acc0);                                   \
        acc1 = fma2(h3, WT[3], acc1);                                   \
        acc0 = fma2(h4, WT[4], acc0);                                   \
        acc1 = fma2(h5, WT[5], acc1);                                   \
        acc0 = fma2(h6, WT[6], acc0);                                   \
        acc1 = fma2(h7, WT[7], acc1);                                   \
        acc0 = add2(acc0, acc1);                                        \
        float zlo, zhi;                                                 \
        asm("mov.b64 {%0, %1}, %2;" : "=f"(zlo), "=f"(zhi) : "l"(acc0));\
        float z = zlo + zhi;                                            \
        float q = z * TWO_LOG2E;                                        \
        float e;                                                        \
        asm("ex2.approx.f32 %0, %1;" : "=f"(e) : "f"(q));               \
        float dd = e + 1.0f;                                            \
        float rc;                                                       \
        asm("rcp.approx.f32 %0, %1;" : "=f"(rc) : "f"(dd));             \
        HOUT = fmaf(-2.0f, rc, 1.0f);                                   \
    } while (0)

#define STEP_TAIL(XV)                                                   \
    do {                                                                \
        unsigned long long h0, h1, h2, h3, h4, h5, h6, h7;              \
        lds_v2u64(h0, h1, rowb + 0);                                    \
        lds_v2u64(h2, h3, rowb + 16);                                   \
        lds_v2u64(h4, h5, rowb + 32);                                   \
        lds_v2u64(h6, h7, rowb + 48);                                   \
        TAILROW(Wt0, qw0, qb0, XV, ha);                                 \
        TAILROW(Wt1, qw1, qb1, XV, hb);                                 \
        TAILROW(Wt2, qw2, qb2, XV, hc);                                 \
        TAILROW(Wt3, qw3, qb3, XV, hd);                                 \
        sts_v4f32(stb, ha, hb, hc, hd);                                 \
    } while (0)

#pragma unroll 1
    for (int t4 = 0; t4 < 16; ++t4) {      // steps 448..511
        float4 tmp = (t4 < 14) ? *(const float4*)(xrt + (t4 + 2) * 4) : nxtt;
        STEP_TAIL(curt.x);
        STEP_TAIL(curt.y);
        STEP_TAIL(curt.z);
        STEP_TAIL(curt.w);
        curt = nxtt;  nxtt = tmp;
    }
#undef STEP_TAIL
#undef TAILROW

    // ==================== Epilogue ====================
    // out[batch0+r] = sum_j h_j * Wfc[j] + bfc ; lane holds rows 4m..4m+3.
    float p = ha * Wfc[4 * m + 0] + hb * Wfc[4 * m + 1]
            + hc * Wfc[4 * m + 2] + hd * Wfc[4 * m + 3];
    p += __shfl_xor_sync(0xffffffffu, p, 2);
    p += __shfl_xor_sync(0xffffffffu, p, 1);
    if (m == 0)
        out[batch0 + r] = p + bfc[0];
}

extern "C" void kernel_launch(void* const* d_in, const int* in_sizes, int n_in,
                              void* d_out, int out_size) {
    const float* x   = (const float*)d_in[0];
    const float* Wih = (const float*)d_in[1];
    const float* Whh = (const float*)d_in[2];
    const float* bih = (const float*)d_in[3];
    const float* bhh = (const float*)d_in[4];
    const float* Wfc = (const float*)d_in[5];
    const float* bfc = (const float*)d_in[6];
    float* out = (float*)d_out;

    // 4096 batches / (4 warps x 8 batches) = 128 blocks of 128 threads
    rnn_kernel<<<128, 128>>>(x, Wih, Whh, bih, bhh, Wfc, bfc, out);
}